// round 2
// baseline (speedup 1.0000x reference)
#include <cuda_runtime.h>
#include <math.h>

#define Bc 2048
#define Dc 24
#define Hc 256
#define Lc 64
#define Vc 780
#define Tc 23               /* D-1 steps per scan direction */
#define Sc 47               /* 2D-1 p-rows per tree */
#define DB (Dc*Bc)          /* 49152 */
#define TB (Tc*Bc)          /* 47104 */
#define SB (Sc*Bc)          /* 96256 */
#define QBLOCKS (DB/8)      /* 6144 */
#define PBLOCKS (SB/8)      /* 12032 */

// ---------------- scratch (static device allocations; no runtime alloc) ----
__device__ float g_Az[DB*Hc];      // x @ Wz[:, :H]^T + bz   [D][B][H]
__device__ float g_Ah[DB*Hc];      // x @ Wh[:, :H]^T + bh
__device__ float g_Ar[DB*Hc];      // x @ Wr^T + br
__device__ float g_Px[DB*Hc];      // x @ U_w[:, :H]^T
__device__ float g_mf[TB*Hc];      // forward messages m_f[t][B][H]
__device__ float g_mr[TB*Hc];      // reverse messages m_r[t][B][H]
__device__ float g_rmf[Bc*Hc];     // r*m carry, forward dir
__device__ float g_rmr[Bc*Hc];     // r*m carry, reverse dir
__device__ float g_Pq [TB*Hc];     // m_f @ W_w[:, :H]^T
__device__ float g_Pmf[TB*Hc];     // m_f @ U_w[:, H:2H]^T
__device__ float g_Pmr[TB*Hc];     // m_r @ U_w[:, H:2H]^T
__device__ float g_Tq[Bc*Hc];      // tree_vec @ W_w[:, H:H+L]^T + W_b
__device__ float g_Tp[Bc*Hc];      // tree_vec @ U_w[:, 2H:2H+L]^T + U_b
__device__ float g_logits[(size_t)DB*Vc];
__device__ float g_qpart_loss[QBLOCKS];
__device__ float g_qpart_corr[QBLOCKS];
__device__ float g_ppart_loss[PBLOCKS];
__device__ float g_ppart_corr[PBLOCKS];

__device__ __forceinline__ float sigf(float x) { return 1.f / (1.f + expf(-x)); }

// ------------- shared 64x64 fp32 GEMM tile core, K=256 ---------------------
// arow/brow: per-thread row pointers (already offset to this thread's load
// row, contiguous along k). nullptr -> zeros. acc[i][j]: rows ty*4+i, cols tx*4+j.
__device__ __forceinline__ void gemm_k256(
    const float* __restrict__ arow, const float* __restrict__ brow,
    float (*As)[64], float (*Bs)[64],
    int lr, int lk, int tx, int ty, float acc[4][4])
{
    for (int k0 = 0; k0 < Hc; k0 += 16) {
        float4 av = make_float4(0.f, 0.f, 0.f, 0.f);
        float4 bv = make_float4(0.f, 0.f, 0.f, 0.f);
        if (arow) av = *(const float4*)(arow + k0 + lk);
        if (brow) bv = *(const float4*)(brow + k0 + lk);
        As[lk + 0][lr] = av.x; As[lk + 1][lr] = av.y;
        As[lk + 2][lr] = av.z; As[lk + 3][lr] = av.w;
        Bs[lk + 0][lr] = bv.x; Bs[lk + 1][lr] = bv.y;
        Bs[lk + 2][lr] = bv.z; Bs[lk + 3][lr] = bv.w;
        __syncthreads();
#pragma unroll
        for (int k = 0; k < 16; k++) {
            float4 a = *(const float4*)(&As[k][ty * 4]);
            float4 b = *(const float4*)(&Bs[k][tx * 4]);
            acc[0][0] += a.x * b.x; acc[0][1] += a.x * b.y; acc[0][2] += a.x * b.z; acc[0][3] += a.x * b.w;
            acc[1][0] += a.y * b.x; acc[1][1] += a.y * b.y; acc[1][2] += a.y * b.z; acc[1][3] += a.y * b.w;
            acc[2][0] += a.z * b.x; acc[2][1] += a.z * b.y; acc[2][2] += a.z * b.z; acc[2][3] += a.z * b.w;
            acc[3][0] += a.w * b.x; acc[3][1] += a.w * b.y; acc[3][2] += a.w * b.z; acc[3][3] += a.w * b.w;
        }
        __syncthreads();
    }
}

// ------------- precompute x-side products (gathered emb rows) --------------
// z=0: Wz[:, :H]+bz -> g_Az   z=1: Wh[:, :H]+bh -> g_Ah
// z=2: Wr+br        -> g_Ar   z=3: U_w[:, :H]   -> g_Px
__global__ void k_precompute_x(
    const int* __restrict__ wid, const float* __restrict__ emb,
    const float* __restrict__ Wz, const float* __restrict__ bz,
    const float* __restrict__ Wh, const float* __restrict__ bh,
    const float* __restrict__ Wr, const float* __restrict__ br,
    const float* __restrict__ U_w)
{
    __shared__ __align__(16) float As[16][64];
    __shared__ __align__(16) float Bs[16][64];
    int tid = threadIdx.x, tx = tid & 15, ty = tid >> 4;
    int lr = tid >> 2, lk = (tid & 3) << 2;
    int rowBase = blockIdx.x * 64, colBase = blockIdx.y * 64;
    int z = blockIdx.z;

    const float* W; int ld; const float* bias; float* out;
    if      (z == 0) { W = Wz;  ld = 2*Hc;      bias = bz; out = g_Az; }
    else if (z == 1) { W = Wh;  ld = 2*Hc;      bias = bh; out = g_Ah; }
    else if (z == 2) { W = Wr;  ld = Hc;        bias = br; out = g_Ar; }
    else             { W = U_w; ld = 2*Hc + Lc; bias = 0;  out = g_Px; }

    int r = rowBase + lr;
    int d = r >> 11, b = r & (Bc - 1);
    const float* arow = emb + (size_t)wid[b * Dc + d] * Hc;
    const float* brow = W + (size_t)(colBase + lr) * ld;

    float acc[4][4] = {};
    gemm_k256(arow, brow, As, Bs, lr, lk, tx, ty, acc);

#pragma unroll
    for (int i = 0; i < 4; i++) {
        int rr = rowBase + ty * 4 + i;
        int cc = colBase + tx * 4;
        float4 o;
        float b0 = bias ? bias[cc + 0] : 0.f, b1 = bias ? bias[cc + 1] : 0.f;
        float b2 = bias ? bias[cc + 2] : 0.f, b3 = bias ? bias[cc + 3] : 0.f;
        o.x = acc[i][0] + b0; o.y = acc[i][1] + b1;
        o.z = acc[i][2] + b2; o.w = acc[i][3] + b3;
        *(float4*)(out + (size_t)rr * Hc + cc) = o;
    }
}

// ------------- tree_vec small GEMMs ----------------------------------------
__global__ void k_tree(const float* __restrict__ tv,
                       const float* __restrict__ W_w, const float* __restrict__ W_b,
                       const float* __restrict__ U_w, const float* __restrict__ U_b)
{
    int b = blockIdx.x, z = blockIdx.y, n = threadIdx.x;
    __shared__ float s_tv[Lc];
    if (n < Lc) s_tv[n] = tv[(size_t)b * Lc + n];
    __syncthreads();
    const float* W; int ld, koff; const float* bias; float* out;
    if (z == 0) { W = W_w; ld = Hc + Lc;     koff = Hc;     bias = W_b; out = g_Tq; }
    else        { W = U_w; ld = 2*Hc + Lc;   koff = 2*Hc;   bias = U_b; out = g_Tp; }
    const float* wr = W + (size_t)n * ld + koff;
    float s = bias[n];
#pragma unroll
    for (int k = 0; k < Lc; k += 4) {
        float4 w4 = *(const float4*)(wr + k);
        s += s_tv[k]*w4.x + s_tv[k+1]*w4.y + s_tv[k+2]*w4.z + s_tv[k+3]*w4.w;
    }
    out[(size_t)b * Hc + n] = s;
}

// ------------- scan phase A: z/mt GEMMs + GRU update -----------------------
__global__ void k_scanA(int t, const float* __restrict__ Wz, const float* __restrict__ Wh)
{
    __shared__ __align__(16) float As[16][64];
    __shared__ __align__(16) float Bs[16][64];
    int tid = threadIdx.x, tx = tid & 15, ty = tid >> 4;
    int lr = tid >> 2, lk = (tid & 3) << 2;
    int rowBase = blockIdx.x * 64, colBase = blockIdx.y * 64;
    int dir = rowBase >= Bc;
    int rb = rowBase - (dir ? Bc : 0);
    int srcd = dir ? (Tc - t) : t;

    const float* Az = g_Az + ((size_t)srcd * Bc + rb) * Hc;
    const float* Ah = g_Ah + ((size_t)srcd * Bc + rb) * Hc;
    const float* mbase = dir ? g_mr : g_mf;
    const float* mprev  = (t > 0) ? mbase + ((size_t)(t-1) * Bc + rb) * Hc : (const float*)0;
    const float* rmprev = (t > 0) ? ((dir ? g_rmr : g_rmf) + (size_t)rb * Hc) : (const float*)0;
    float* mout = (dir ? g_mr : g_mf) + ((size_t)t * Bc + rb) * Hc;

    float accz[4][4] = {}, acch[4][4] = {};
    if (t > 0) {
        const float* uzrow = Wz + (size_t)(colBase + lr) * (2*Hc) + Hc;
        const float* uhrow = Wh + (size_t)(colBase + lr) * (2*Hc) + Hc;
        gemm_k256(mprev  + (size_t)lr * Hc, uzrow, As, Bs, lr, lk, tx, ty, accz);
        gemm_k256(rmprev + (size_t)lr * Hc, uhrow, As, Bs, lr, lk, tx, ty, acch);
    }

#pragma unroll
    for (int i = 0; i < 4; i++) {
        int q = ty * 4 + i;
        int c = colBase + tx * 4;
        float4 az4 = *(const float4*)(Az + (size_t)q * Hc + c);
        float4 ah4 = *(const float4*)(Ah + (size_t)q * Hc + c);
        float4 mp4 = (t > 0) ? *(const float4*)(mprev + (size_t)q * Hc + c)
                             : make_float4(0.f, 0.f, 0.f, 0.f);
        float4 o;
        {
            float zz = sigf(accz[i][0] + az4.x), mt = tanhf(acch[i][0] + ah4.x);
            o.x = (1.f - zz) * mp4.x + zz * mt;
        }
        {
            float zz = sigf(accz[i][1] + az4.y), mt = tanhf(acch[i][1] + ah4.y);
            o.y = (1.f - zz) * mp4.y + zz * mt;
        }
        {
            float zz = sigf(accz[i][2] + az4.z), mt = tanhf(acch[i][2] + ah4.z);
            o.z = (1.f - zz) * mp4.z + zz * mt;
        }
        {
            float zz = sigf(accz[i][3] + az4.w), mt = tanhf(acch[i][3] + ah4.w);
            o.w = (1.f - zz) * mp4.w + zz * mt;
        }
        *(float4*)(mout + (size_t)q * Hc + c) = o;
    }
}

// ------------- scan phase B: r GEMM + r*m carry ----------------------------
__global__ void k_scanB(int t, const float* __restrict__ Ur)
{
    __shared__ __align__(16) float As[16][64];
    __shared__ __align__(16) float Bs[16][64];
    int tid = threadIdx.x, tx = tid & 15, ty = tid >> 4;
    int lr = tid >> 2, lk = (tid & 3) << 2;
    int rowBase = blockIdx.x * 64, colBase = blockIdx.y * 64;
    int dir = rowBase >= Bc;
    int rb = rowBase - (dir ? Bc : 0);
    int dstd = dir ? (Tc - 1 - t) : (t + 1);

    const float* Ar = g_Ar + ((size_t)dstd * Bc + rb) * Hc;
    const float* mcur = (dir ? g_mr : g_mf) + ((size_t)t * Bc + rb) * Hc;
    float* rmout = (dir ? g_rmr : g_rmf) + (size_t)rb * Hc;

    float acc[4][4] = {};
    gemm_k256(mcur + (size_t)lr * Hc, Ur + (size_t)(colBase + lr) * Hc,
              As, Bs, lr, lk, tx, ty, acc);

#pragma unroll
    for (int i = 0; i < 4; i++) {
        int q = ty * 4 + i;
        int c = colBase + tx * 4;
        float4 ar4 = *(const float4*)(Ar + (size_t)q * Hc + c);
        float4 m4  = *(const float4*)(mcur + (size_t)q * Hc + c);
        float4 o;
        o.x = sigf(acc[i][0] + ar4.x) * m4.x;
        o.y = sigf(acc[i][1] + ar4.y) * m4.y;
        o.z = sigf(acc[i][2] + ar4.z) * m4.z;
        o.w = sigf(acc[i][3] + ar4.w) * m4.w;
        *(float4*)(rmout + (size_t)q * Hc + c) = o;
    }
}

// ------------- message-side products ---------------------------------------
// z=0: m_f @ W_w[:, :H]^T -> g_Pq   z=1: m_f @ U_w[:, H:2H]^T -> g_Pmf
// z=2: m_r @ U_w[:, H:2H]^T -> g_Pmr
__global__ void k_postm(const float* __restrict__ W_w, const float* __restrict__ U_w)
{
    __shared__ __align__(16) float As[16][64];
    __shared__ __align__(16) float Bs[16][64];
    int tid = threadIdx.x, tx = tid & 15, ty = tid >> 4;
    int lr = tid >> 2, lk = (tid & 3) << 2;
    int rowBase = blockIdx.x * 64, colBase = blockIdx.y * 64;
    int z = blockIdx.z;

    const float* A; const float* W; int ld, koff; float* out;
    if      (z == 0) { A = g_mf; W = W_w; ld = Hc + Lc;   koff = 0;  out = g_Pq;  }
    else if (z == 1) { A = g_mf; W = U_w; ld = 2*Hc + Lc; koff = Hc; out = g_Pmf; }
    else             { A = g_mr; W = U_w; ld = 2*Hc + Lc; koff = Hc; out = g_Pmr; }

    const float* arow = A + (size_t)(rowBase + lr) * Hc;
    const float* brow = W + (size_t)(colBase + lr) * ld + koff;
    float acc[4][4] = {};
    gemm_k256(arow, brow, As, Bs, lr, lk, tx, ty, acc);

#pragma unroll
    for (int i = 0; i < 4; i++) {
        int rr = rowBase + ty * 4 + i;
        int cc = colBase + tx * 4;
        float4 o = make_float4(acc[i][0], acc[i][1], acc[i][2], acc[i][3]);
        *(float4*)(out + (size_t)rr * Hc + cc) = o;
    }
}

// ------------- q logits GEMM with fused q1 assembly ------------------------
__global__ void k_logits(const float* __restrict__ Wo, const float* __restrict__ Wob)
{
    __shared__ __align__(16) float As[16][64];
    __shared__ __align__(16) float Bs[16][64];
    int tid = threadIdx.x, tx = tid & 15, ty = tid >> 4;
    int lr = tid >> 2, lk = (tid & 3) << 2;
    int rowBase = blockIdx.x * 64, colBase = blockIdx.y * 64;

    int r = rowBase + lr;
    int d = r >> 11, b = r & (Bc - 1);
    const float* pq = d ? (g_Pq + ((size_t)(d - 1) * Bc + b) * Hc) : (const float*)0;
    const float* tq = g_Tq + (size_t)b * Hc;
    int wrow = colBase + lr;
    const float* brow = (wrow < Vc) ? (Wo + (size_t)wrow * Hc) : (const float*)0;

    float acc[4][4] = {};
    for (int k0 = 0; k0 < Hc; k0 += 16) {
        float4 av = *(const float4*)(tq + k0 + lk);
        if (pq) {
            float4 p4 = *(const float4*)(pq + k0 + lk);
            av.x += p4.x; av.y += p4.y; av.z += p4.z; av.w += p4.w;
        }
        av.x = fmaxf(av.x, 0.f); av.y = fmaxf(av.y, 0.f);
        av.z = fmaxf(av.z, 0.f); av.w = fmaxf(av.w, 0.f);
        float4 bv = brow ? *(const float4*)(brow + k0 + lk) : make_float4(0.f,0.f,0.f,0.f);
        As[lk + 0][lr] = av.x; As[lk + 1][lr] = av.y;
        As[lk + 2][lr] = av.z; As[lk + 3][lr] = av.w;
        Bs[lk + 0][lr] = bv.x; Bs[lk + 1][lr] = bv.y;
        Bs[lk + 2][lr] = bv.z; Bs[lk + 3][lr] = bv.w;
        __syncthreads();
#pragma unroll
        for (int k = 0; k < 16; k++) {
            float4 a = *(const float4*)(&As[k][ty * 4]);
            float4 bb = *(const float4*)(&Bs[k][tx * 4]);
            acc[0][0] += a.x * bb.x; acc[0][1] += a.x * bb.y; acc[0][2] += a.x * bb.z; acc[0][3] += a.x * bb.w;
            acc[1][0] += a.y * bb.x; acc[1][1] += a.y * bb.y; acc[1][2] += a.y * bb.z; acc[1][3] += a.y * bb.w;
            acc[2][0] += a.z * bb.x; acc[2][1] += a.z * bb.y; acc[2][2] += a.z * bb.z; acc[2][3] += a.z * bb.w;
            acc[3][0] += a.w * bb.x; acc[3][1] += a.w * bb.y; acc[3][2] += a.w * bb.z; acc[3][3] += a.w * bb.w;
        }
        __syncthreads();
    }

#pragma unroll
    for (int i = 0; i < 4; i++) {
        int rr = rowBase + ty * 4 + i;
#pragma unroll
        for (int j = 0; j < 4; j++) {
            int cc = colBase + tx * 4 + j;
            if (cc < Vc)
                g_logits[(size_t)rr * Vc + cc] = acc[i][j] + Wob[cc];
        }
    }
}

// ------------- q-head reduction: logsumexp / argmax / loss -----------------
__global__ void k_qreduce(const int* __restrict__ wid)
{
    int warp = threadIdx.x >> 5, lane = threadIdx.x & 31;
    int row = blockIdx.x * 8 + warp;
    const float* qr = g_logits + (size_t)row * Vc;

    float bv = -3.4e38f; int bi = Vc;
    for (int j = lane; j < Vc; j += 32) {
        float v = qr[j];
        if (v > bv) { bv = v; bi = j; }
    }
#pragma unroll
    for (int o = 16; o; o >>= 1) {
        float ov = __shfl_xor_sync(0xffffffffu, bv, o);
        int   oi = __shfl_xor_sync(0xffffffffu, bi, o);
        if (ov > bv || (ov == bv && oi < bi)) { bv = ov; bi = oi; }
    }
    float se = 0.f;
    for (int j = lane; j < Vc; j += 32) se += expf(qr[j] - bv);
#pragma unroll
    for (int o = 16; o; o >>= 1) se += __shfl_xor_sync(0xffffffffu, se, o);

    __shared__ float sl[8], sc[8];
    if (lane == 0) {
        int d = row >> 11, b = row & (Bc - 1);
        int tgt = wid[b * Dc + d];
        float sel = qr[tgt];
        sl[warp] = (bv + logf(se)) - sel;
        sc[warp] = (bi == tgt) ? 1.f : 0.f;
    }
    __syncthreads();
    if (threadIdx.x == 0) {
        float a = 0.f, c = 0.f;
        for (int w = 0; w < 8; w++) { a += sl[w]; c += sc[w]; }
        g_qpart_loss[blockIdx.x] = a;
        g_qpart_corr[blockIdx.x] = c;
    }
}

// ------------- p-head: assemble + relu + GEMV + BCE ------------------------
__global__ void k_p(const float* __restrict__ usw, const float* __restrict__ usb)
{
    int warp = threadIdx.x >> 5, lane = threadIdx.x & 31;
    int row = blockIdx.x * 8 + warp;
    int s = row >> 11, b = row & (Bc - 1);

    int xd, c1, c2;
    if (s == 0)       { xd = 0;        c1 = -1;                         c2 = -1; }
    else if (s <= Tc) { xd = s;        c1 = s - 1;                      c2 = -1; }
    else { int j = s - (Tc + 1); xd = Tc - 1 - j; c1 = (j <= Tc - 2) ? (Tc - 2 - j) : -1; c2 = j; }

    const float* px = g_Px + ((size_t)xd * Bc + b) * Hc;
    const float* tp = g_Tp + (size_t)b * Hc;
    const float* f1 = (c1 >= 0) ? (g_Pmf + ((size_t)c1 * Bc + b) * Hc) : (const float*)0;
    const float* f2 = (c2 >= 0) ? (g_Pmr + ((size_t)c2 * Bc + b) * Hc) : (const float*)0;

    float acc = 0.f;
#pragma unroll
    for (int i = 0; i < 2; i++) {
        int n = (lane + 32 * i) * 4;
        float4 v = *(const float4*)(px + n);
        float4 t4 = *(const float4*)(tp + n);
        v.x += t4.x; v.y += t4.y; v.z += t4.z; v.w += t4.w;
        if (f1) { float4 a4 = *(const float4*)(f1 + n); v.x += a4.x; v.y += a4.y; v.z += a4.z; v.w += a4.w; }
        if (f2) { float4 a4 = *(const float4*)(f2 + n); v.x += a4.x; v.y += a4.y; v.z += a4.z; v.w += a4.w; }
        v.x = fmaxf(v.x, 0.f); v.y = fmaxf(v.y, 0.f);
        v.z = fmaxf(v.z, 0.f); v.w = fmaxf(v.w, 0.f);
        float4 u = *(const float4*)(usw + n);
        acc += v.x*u.x + v.y*u.y + v.z*u.z + v.w*u.w;
    }
#pragma unroll
    for (int o = 16; o; o >>= 1) acc += __shfl_xor_sync(0xffffffffu, acc, o);

    __shared__ float sl[8], sc[8];
    if (lane == 0) {
        float p = acc + usb[0];
        int tchk = (s < Tc) ? 1 : 0;
        float loss = fmaxf(p, 0.f) - (tchk ? p : 0.f) + log1pf(expf(-fabsf(p)));
        float corr = (((p > 0.f) ? 1 : 0) == tchk) ? 1.f : 0.f;
        sl[warp] = loss; sc[warp] = corr;
    }
    __syncthreads();
    if (threadIdx.x == 0) {
        float a = 0.f, c = 0.f;
        for (int w = 0; w < 8; w++) { a += sl[w]; c += sc[w]; }
        g_ppart_loss[blockIdx.x] = a;
        g_ppart_corr[blockIdx.x] = c;
    }
}

// ------------- final deterministic reduction -------------------------------
__global__ void k_finalize(float* __restrict__ out)
{
    __shared__ float sq[256], sqc[256], sp[256], spc[256];
    int t = threadIdx.x;
    float a = 0.f, b = 0.f, c = 0.f, d = 0.f;
    for (int i = t; i < QBLOCKS; i += 256) { a += g_qpart_loss[i]; b += g_qpart_corr[i]; }
    for (int i = t; i < PBLOCKS; i += 256) { c += g_ppart_loss[i]; d += g_ppart_corr[i]; }
    sq[t] = a; sqc[t] = b; sp[t] = c; spc[t] = d;
    __syncthreads();
    for (int o = 128; o; o >>= 1) {
        if (t < o) { sq[t] += sq[t+o]; sqc[t] += sqc[t+o]; sp[t] += sp[t+o]; spc[t] += spc[t+o]; }
        __syncthreads();
    }
    if (t == 0) {
        out[0] = sq[0]  / (float)Bc;   // q_loss
        out[1] = sp[0]  / (float)Bc;   // p_loss
        out[2] = sqc[0] / (float)DB;   // q_acc
        out[3] = spc[0] / (float)SB;   // p_acc
    }
}

// ---------------------------------------------------------------------------
extern "C" void kernel_launch(void* const* d_in, const int* in_sizes, int n_in,
                              void* d_out, int out_size)
{
    const int*   wid      = (const int*)  d_in[0];
    const float* tree_vec = (const float*)d_in[1];
    const float* emb      = (const float*)d_in[2];
    const float* Wz       = (const float*)d_in[3];
    const float* bz       = (const float*)d_in[4];
    const float* Wr       = (const float*)d_in[5];
    const float* Ur       = (const float*)d_in[6];
    const float* br       = (const float*)d_in[7];
    const float* Wh       = (const float*)d_in[8];
    const float* bh       = (const float*)d_in[9];
    const float* W_w      = (const float*)d_in[10];
    const float* W_b      = (const float*)d_in[11];
    const float* U_w      = (const float*)d_in[12];
    const float* U_b      = (const float*)d_in[13];
    const float* Wo_w     = (const float*)d_in[14];
    const float* Wo_b     = (const float*)d_in[15];
    const float* Us_w     = (const float*)d_in[16];
    const float* Us_b     = (const float*)d_in[17];
    float* out = (float*)d_out;

    k_precompute_x<<<dim3(DB/64, Hc/64, 4), 256>>>(wid, emb, Wz, bz, Wh, bh, Wr, br, U_w);
    k_tree<<<dim3(Bc, 2), 256>>>(tree_vec, W_w, W_b, U_w, U_b);

    for (int t = 0; t < Tc; t++) {
        k_scanA<<<dim3(2*Bc/64, Hc/64), 256>>>(t, Wz, Wh);
        if (t < Tc - 1)
            k_scanB<<<dim3(2*Bc/64, Hc/64), 256>>>(t, Ur);
    }

    k_postm<<<dim3(TB/64, Hc/64, 3), 256>>>(W_w, U_w);
    k_logits<<<dim3(DB/64, (Vc + 63)/64), 256>>>(Wo_w, Wo_b);
    k_qreduce<<<QBLOCKS, 256>>>(wid);
    k_p<<<PBLOCKS, 256>>>(Us_w, Us_b);
    k_finalize<<<1, 256>>>(out);
}

// round 4
// speedup vs baseline: 1.8764x; 1.8764x over previous
#include <cuda_runtime.h>
#include <cuda_bf16.h>
#include <math.h>
#include <stdint.h>

#define Bc 2048
#define Dc 24
#define Hc 256
#define Lc 64
#define Vc 780
#define Tc 23
#define Sc 47
#define DB (Dc*Bc)
#define TB (Tc*Bc)
#define SB (Sc*Bc)
#define QBLOCKS (DB/8)
#define PBLOCKS (SB/8)
#define WROWS 3200

// ---------------- fp32 scratch ---------------------------------------------
__device__ float g_Az[DB*Hc];
__device__ float g_Ah[DB*Hc];
__device__ float g_Ar[DB*Hc];
__device__ float g_Px[DB*Hc];
__device__ float g_mf[TB*Hc];
__device__ float g_mr[TB*Hc];
__device__ float g_Pq [TB*Hc];
__device__ float g_Pmf[TB*Hc];
__device__ float g_Pmr[TB*Hc];
__device__ float g_Tq[Bc*Hc];
__device__ float g_Tp[Bc*Hc];
__device__ float g_logits[(size_t)DB*Vc];
__device__ float g_qpart_loss[QBLOCKS];
__device__ float g_qpart_corr[QBLOCKS];
__device__ float g_ppart_loss[PBLOCKS];
__device__ float g_ppart_corr[PBLOCKS];
// bf16 split planes
__device__ __nv_bfloat16 g_wH[(size_t)WROWS*Hc];
__device__ __nv_bfloat16 g_wL[(size_t)WROWS*Hc];
__device__ __nv_bfloat16 g_eH[(size_t)Vc*Hc];
__device__ __nv_bfloat16 g_eL[(size_t)Vc*Hc];
__device__ __nv_bfloat16 g_mH[(size_t)2*TB*Hc];   // [dir][t*Bc+b][Hc]
__device__ __nv_bfloat16 g_mL[(size_t)2*TB*Hc];
__device__ __nv_bfloat16 g_rmH[(size_t)2*Bc*Hc];  // [dir][b][Hc]
__device__ __nv_bfloat16 g_rmL[(size_t)2*Bc*Hc];

__device__ __forceinline__ float sigf(float x) { return 1.f / (1.f + expf(-x)); }

// =================== mma.sync core (sm_80+ path; no tcgen05) ===============
__device__ __forceinline__ uint32_t s2u(const void* p) {
    uint32_t a;
    asm("{ .reg .u64 t; cvta.to.shared.u64 t, %1; cvt.u32.u64 %0, t; }" : "=r"(a) : "l"(p));
    return a;
}
__device__ __forceinline__ void ldsm4(uint32_t& r0, uint32_t& r1, uint32_t& r2, uint32_t& r3, uint32_t a) {
    asm volatile("ldmatrix.sync.aligned.m8n8.x4.shared.b16 {%0,%1,%2,%3}, [%4];"
        : "=r"(r0), "=r"(r1), "=r"(r2), "=r"(r3) : "r"(a));
}
__device__ __forceinline__ void mma16816(float* d,
    uint32_t a0, uint32_t a1, uint32_t a2, uint32_t a3, uint32_t b0, uint32_t b1) {
    asm volatile("mma.sync.aligned.m16n8k16.row.col.f32.bf16.bf16.f32 "
        "{%0,%1,%2,%3}, {%4,%5,%6,%7}, {%8,%9}, {%0,%1,%2,%3};"
        : "+f"(d[0]), "+f"(d[1]), "+f"(d[2]), "+f"(d[3])
        : "r"(a0), "r"(a1), "r"(a2), "r"(a3), "r"(b0), "r"(b1));
}
// warp 32x32 product pass: A tile stride 80B (40 bf16), B tile stride 80B.
// aAddr/bAddr: smem addrs already including lane & warp offsets for this kk.
__device__ __forceinline__ void pass_mma(uint32_t aAddr, uint32_t bAddr, float acc[2][4][4]) {
    uint32_t b0, b1, b2, b3, b4, b5, b6, b7;
    ldsm4(b0, b1, b2, b3, bAddr);
    ldsm4(b4, b5, b6, b7, bAddr + 1280);
#pragma unroll
    for (int mf = 0; mf < 2; mf++) {
        uint32_t a0, a1, a2, a3;
        ldsm4(a0, a1, a2, a3, aAddr + mf * 1280);
        mma16816(acc[mf][0], a0, a1, a2, a3, b0, b1);
        mma16816(acc[mf][1], a0, a1, a2, a3, b2, b3);
        mma16816(acc[mf][2], a0, a1, a2, a3, b4, b5);
        mma16816(acc[mf][3], a0, a1, a2, a3, b6, b7);
    }
}
__device__ __forceinline__ uint32_t aLaneOff(int lane, int wm) {
    return (uint32_t)((lane & 15) * 80 + (lane >> 4) * 16 + wm * 2560);
}
__device__ __forceinline__ uint32_t bLaneOff(int lane, int wn) {
    return (uint32_t)((((lane & 7) + ((lane >> 4) & 1) * 8)) * 80 + ((lane >> 3) & 1) * 16 + wn * 2560);
}
__device__ __forceinline__ uint32_t packbf2(float a, float b) {
    __nv_bfloat162 v = __floats2bfloat162_rn(a, b);
    return *(uint32_t*)&v;
}

// ------------- split/convert kernels ---------------------------------------
// weight pack rows: [0,256) Wz[:, :H] | [256,512) Wh[:, :H] | [512,768) Wr |
// [768,1024) U_w[:, :H] | [1024,1280) W_w[:, :H] | [1280,1536) U_w[:, H:2H] |
// [1536,2432) Wo (pad to 896) | [2432,2688) Uz=Wz[:,H:] | [2688,2944) Uh=Wh[:,H:] |
// [2944,3200) Ur
__global__ void k_split_w(const float* __restrict__ Wz, const float* __restrict__ Wh,
                          const float* __restrict__ Wr, const float* __restrict__ Ur,
                          const float* __restrict__ U_w, const float* __restrict__ W_w,
                          const float* __restrict__ Wo_w)
{
    int r = blockIdx.x, c = threadIdx.x;
    float v;
    if      (r < 256)  v = Wz[r * 512 + c];
    else if (r < 512)  v = Wh[(r - 256) * 512 + c];
    else if (r < 768)  v = Wr[(r - 512) * 256 + c];
    else if (r < 1024) v = U_w[(r - 768) * 576 + c];
    else if (r < 1280) v = W_w[(r - 1024) * 320 + c];
    else if (r < 1536) v = U_w[(r - 1280) * 576 + 256 + c];
    else if (r < 2432) { int w = r - 1536; v = (w < Vc) ? Wo_w[(size_t)w * 256 + c] : 0.f; }
    else if (r < 2688) v = Wz[(r - 2432) * 512 + 256 + c];
    else if (r < 2944) v = Wh[(r - 2688) * 512 + 256 + c];
    else               v = Ur[(r - 2944) * 256 + c];
    __nv_bfloat16 h = __float2bfloat16(v);
    g_wH[(size_t)r * 256 + c] = h;
    g_wL[(size_t)r * 256 + c] = __float2bfloat16(v - __bfloat162float(h));
}

__global__ void k_split_emb(const float* __restrict__ emb)
{
    int r = blockIdx.x, c = threadIdx.x;
    float v = emb[(size_t)r * 256 + c];
    __nv_bfloat16 h = __float2bfloat16(v);
    g_eH[(size_t)r * 256 + c] = h;
    g_eL[(size_t)r * 256 + c] = __float2bfloat16(v - __bfloat162float(h));
}

// ------------- generic big GEMM (HMMA, CTA 128x64, warp 32x32) -------------
// mode 0-3: A=emb[wid] planes, W seg {0,256,512,768}, out Az/Ah/Ar/Px (+bias)
// mode 4-6: A=m planes, seg {1024,1280,1280}, out Pq/Pmf/Pmr
// mode 7:   A=relu(Pq[d-1]+Tq) split on the fly, seg 1536, out logits (+Wo_b)
#define TCG_AH 0
#define TCG_AL 10240
#define TCG_BH 20480
#define TCG_BL 25600
#define TCG_DSM 33792
__global__ void k_tcg(int modeBase, const int* __restrict__ wid,
                      const float* __restrict__ bz, const float* __restrict__ bh,
                      const float* __restrict__ br, const float* __restrict__ Wob)
{
    extern __shared__ char smc[];
    uint32_t smb = s2u(smc);
    int tid = threadIdx.x, lane = tid & 31, warp = tid >> 5;
    int wm = warp >> 1, wn = warp & 1;
    int mode = modeBase + blockIdx.z;
    int rowBase = blockIdx.x * 128, colBase = blockIdx.y * 64;

    int wbase; float* outp; const float* bias; int ldout = 256; int nGuard = 1 << 30;
    switch (mode) {
        case 0: wbase = 0;    outp = g_Az;  bias = bz; break;
        case 1: wbase = 256;  outp = g_Ah;  bias = bh; break;
        case 2: wbase = 512;  outp = g_Ar;  bias = br; break;
        case 3: wbase = 768;  outp = g_Px;  bias = 0;  break;
        case 4: wbase = 1024; outp = g_Pq;  bias = 0;  break;
        case 5: wbase = 1280; outp = g_Pmf; bias = 0;  break;
        case 6: wbase = 1280; outp = g_Pmr; bias = 0;  break;
        default: wbase = 1536; outp = g_logits; bias = Wob; ldout = Vc; nGuard = Vc; break;
    }

    const uint4 *aHp[2], *aLp[2];
    const float4 *pqP[2], *tqP[2];
    uint32_t aStore[2];
#pragma unroll
    for (int j = 0; j < 2; j++) {
        int idx = tid + j * 256;
        int row = idx >> 2, q = idx & 3;
        aStore[j] = (uint32_t)(row * 80 + q * 16);
        int rA = rowBase + row;
        if (mode < 4) {
            int d = rA >> 11, b = rA & 2047;
            int sr = wid[b * Dc + d];
            aHp[j] = (const uint4*)(g_eH + (size_t)sr * 256 + q * 8);
            aLp[j] = (const uint4*)(g_eL + (size_t)sr * 256 + q * 8);
        } else if (mode < 7) {
            size_t rs = (size_t)((mode == 6) ? TB : 0) + rA;
            aHp[j] = (const uint4*)(g_mH + rs * 256 + q * 8);
            aLp[j] = (const uint4*)(g_mL + rs * 256 + q * 8);
        } else {
            int d = rA >> 11, b = rA & 2047;
            tqP[j] = (const float4*)(g_Tq + (size_t)b * 256 + q * 8);
            pqP[j] = d ? (const float4*)(g_Pq + ((size_t)(d - 1) * Bc + b) * 256 + q * 8)
                       : (const float4*)0;
        }
    }
    int bRow = tid >> 2, bQ = tid & 3;
    uint32_t bStore = (uint32_t)(bRow * 80 + bQ * 16);
    const uint4* bHp = (const uint4*)(g_wH + (size_t)(wbase + colBase + bRow) * 256 + bQ * 8);
    const uint4* bLp = (const uint4*)(g_wL + (size_t)(wbase + colBase + bRow) * 256 + bQ * 8);

    uint32_t aOff = aLaneOff(lane, wm), bOff = bLaneOff(lane, wn);
    float acc[2][4][4] = {};

    for (int kc = 0; kc < 8; kc++) {
        if (mode < 7) {
#pragma unroll
            for (int j = 0; j < 2; j++) {
                *(uint4*)(smc + TCG_AH + aStore[j]) = aHp[j][kc * 4];
                *(uint4*)(smc + TCG_AL + aStore[j]) = aLp[j][kc * 4];
            }
        } else {
#pragma unroll
            for (int j = 0; j < 2; j++) {
                float4 v0 = tqP[j][kc * 8], v1 = tqP[j][kc * 8 + 1];
                if (pqP[j]) {
                    float4 p0 = pqP[j][kc * 8], p1 = pqP[j][kc * 8 + 1];
                    v0.x += p0.x; v0.y += p0.y; v0.z += p0.z; v0.w += p0.w;
                    v1.x += p1.x; v1.y += p1.y; v1.z += p1.z; v1.w += p1.w;
                }
                float vv[8] = { fmaxf(v0.x,0.f), fmaxf(v0.y,0.f), fmaxf(v0.z,0.f), fmaxf(v0.w,0.f),
                                fmaxf(v1.x,0.f), fmaxf(v1.y,0.f), fmaxf(v1.z,0.f), fmaxf(v1.w,0.f) };
                union { uint4 u; __nv_bfloat16 b[8]; } Hx, Lx;
#pragma unroll
                for (int e = 0; e < 8; e++) {
                    Hx.b[e] = __float2bfloat16(vv[e]);
                    Lx.b[e] = __float2bfloat16(vv[e] - __bfloat162float(Hx.b[e]));
                }
                *(uint4*)(smc + TCG_AH + aStore[j]) = Hx.u;
                *(uint4*)(smc + TCG_AL + aStore[j]) = Lx.u;
            }
        }
        *(uint4*)(smc + TCG_BH + bStore) = bHp[kc * 4];
        *(uint4*)(smc + TCG_BL + bStore) = bLp[kc * 4];
        __syncthreads();
#pragma unroll
        for (int kk = 0; kk < 2; kk++) {
            uint32_t ah = smb + TCG_AH + aOff + kk * 32;
            uint32_t al = smb + TCG_AL + aOff + kk * 32;
            uint32_t bh_ = smb + TCG_BH + bOff + kk * 32;
            uint32_t bl_ = smb + TCG_BL + bOff + kk * 32;
            pass_mma(ah, bh_, acc);
            pass_mma(ah, bl_, acc);
            pass_mma(al, bh_, acc);
        }
        __syncthreads();
    }

    // staged coalesced epilogue
    float* stg = (float*)smc + warp * (32 * 33);
#pragma unroll
    for (int mf = 0; mf < 2; mf++)
#pragma unroll
        for (int nf = 0; nf < 4; nf++) {
            int r = mf * 16 + (lane >> 2);
            int c = nf * 8 + ((lane & 3) << 1);
            stg[r * 33 + c]           = acc[mf][nf][0];
            stg[r * 33 + c + 1]       = acc[mf][nf][1];
            stg[(r + 8) * 33 + c]     = acc[mf][nf][2];
            stg[(r + 8) * 33 + c + 1] = acc[mf][nf][3];
        }
    __syncwarp();
    int colg = colBase + wn * 32 + lane;
    if (colg < nGuard) {
        float bval = bias ? bias[colg] : 0.f;
#pragma unroll 8
        for (int r = 0; r < 32; r++) {
            int rowg = rowBase + wm * 32 + r;
            outp[(size_t)rowg * ldout + colg] = stg[r * 33 + lane] + bval;
        }
    }
}

// ------------- tree_vec small GEMMs ----------------------------------------
__global__ void k_tree(const float* __restrict__ tv,
                       const float* __restrict__ W_w, const float* __restrict__ W_b,
                       const float* __restrict__ U_w, const float* __restrict__ U_b)
{
    int b = blockIdx.x, z = blockIdx.y, n = threadIdx.x;
    __shared__ float s_tv[Lc];
    if (n < Lc) s_tv[n] = tv[(size_t)b * Lc + n];
    __syncthreads();
    const float* W; int ld, koff; const float* bias; float* out;
    if (z == 0) { W = W_w; ld = Hc + Lc;   koff = Hc;   bias = W_b; out = g_Tq; }
    else        { W = U_w; ld = 2*Hc + Lc; koff = 2*Hc; bias = U_b; out = g_Tp; }
    const float* wr = W + (size_t)n * ld + koff;
    float s = bias[n];
#pragma unroll
    for (int k = 0; k < Lc; k += 4) {
        float4 w4 = *(const float4*)(wr + k);
        s += s_tv[k]*w4.x + s_tv[k+1]*w4.y + s_tv[k+2]*w4.z + s_tv[k+3]*w4.w;
    }
    out[(size_t)b * Hc + n] = s;
}

// ------------- scan phase A (HMMA): z/mt GEMMs + GRU update ---------------
// CTA 128x64, warp 32x32. M = 2 dirs x 2048.
#define SA_A1H 0
#define SA_A1L 10240
#define SA_A2H 20480
#define SA_A2L 30720
#define SA_BZH 40960
#define SA_BZL 46080
#define SA_BHH 51200
#define SA_BHL 56320
#define SA_DSM 61440
__global__ void k_scanA(int t)
{
    extern __shared__ char smc[];
    uint32_t smb = s2u(smc);
    int tid = threadIdx.x, lane = tid & 31, warp = tid >> 5;
    int wm = warp >> 1, wn = warp & 1;
    int rowBase = blockIdx.x * 128, colBase = blockIdx.y * 64;
    int dir = rowBase >> 11;
    int rb = rowBase & 2047;
    int srcd = dir ? (Tc - t) : t;

    float accz[2][4][4] = {}, acch[2][4][4] = {};

    if (t > 0) {
        const uint4 *m1H[2], *m1L[2], *m2H[2], *m2L[2];
        uint32_t aStore[2];
#pragma unroll
        for (int j = 0; j < 2; j++) {
            int idx = tid + j * 256;
            int row = idx >> 2, q = idx & 3;
            aStore[j] = (uint32_t)(row * 80 + q * 16);
            size_t pr = (size_t)dir * TB + (size_t)(t - 1) * Bc + rb + row;
            m1H[j] = (const uint4*)(g_mH + pr * 256 + q * 8);
            m1L[j] = (const uint4*)(g_mL + pr * 256 + q * 8);
            size_t rr = (size_t)dir * Bc + rb + row;
            m2H[j] = (const uint4*)(g_rmH + rr * 256 + q * 8);
            m2L[j] = (const uint4*)(g_rmL + rr * 256 + q * 8);
        }
        int bRow = tid >> 2, bQ = tid & 3;
        uint32_t bStore = (uint32_t)(bRow * 80 + bQ * 16);
        const uint4* uzH = (const uint4*)(g_wH + (size_t)(2432 + colBase + bRow) * 256 + bQ * 8);
        const uint4* uzL = (const uint4*)(g_wL + (size_t)(2432 + colBase + bRow) * 256 + bQ * 8);
        const uint4* uhH = (const uint4*)(g_wH + (size_t)(2688 + colBase + bRow) * 256 + bQ * 8);
        const uint4* uhL = (const uint4*)(g_wL + (size_t)(2688 + colBase + bRow) * 256 + bQ * 8);
        uint32_t aOff = aLaneOff(lane, wm), bOff = bLaneOff(lane, wn);

        for (int kc = 0; kc < 8; kc++) {
#pragma unroll
            for (int j = 0; j < 2; j++) {
                *(uint4*)(smc + SA_A1H + aStore[j]) = m1H[j][kc * 4];
                *(uint4*)(smc + SA_A1L + aStore[j]) = m1L[j][kc * 4];
                *(uint4*)(smc + SA_A2H + aStore[j]) = m2H[j][kc * 4];
                *(uint4*)(smc + SA_A2L + aStore[j]) = m2L[j][kc * 4];
            }
            *(uint4*)(smc + SA_BZH + bStore) = uzH[kc * 4];
            *(uint4*)(smc + SA_BZL + bStore) = uzL[kc * 4];
            *(uint4*)(smc + SA_BHH + bStore) = uhH[kc * 4];
            *(uint4*)(smc + SA_BHL + bStore) = uhL[kc * 4];
            __syncthreads();
#pragma unroll
            for (int kk = 0; kk < 2; kk++) {
                uint32_t kb = kk * 32;
                pass_mma(smb + SA_A1H + aOff + kb, smb + SA_BZH + bOff + kb, accz);
                pass_mma(smb + SA_A1H + aOff + kb, smb + SA_BZL + bOff + kb, accz);
                pass_mma(smb + SA_A1L + aOff + kb, smb + SA_BZH + bOff + kb, accz);
                pass_mma(smb + SA_A2H + aOff + kb, smb + SA_BHH + bOff + kb, acch);
                pass_mma(smb + SA_A2H + aOff + kb, smb + SA_BHL + bOff + kb, acch);
                pass_mma(smb + SA_A2L + aOff + kb, smb + SA_BHH + bOff + kb, acch);
            }
            __syncthreads();
        }
    }

    // GRU epilogue on accumulator layout
    const float* mprevF = (t > 0) ? ((dir ? g_mr : g_mf) + (size_t)(t - 1) * Bc * 256) : (const float*)0;
    float* moutF = (dir ? g_mr : g_mf) + (size_t)t * Bc * 256;
    size_t planeRowBase = (size_t)dir * TB + (size_t)t * Bc;
#pragma unroll
    for (int mf = 0; mf < 2; mf++)
#pragma unroll
        for (int nf = 0; nf < 4; nf++) {
            int rl0 = wm * 32 + mf * 16 + (lane >> 2);
            int col = colBase + wn * 32 + nf * 8 + ((lane & 3) << 1);
#pragma unroll
            for (int h = 0; h < 2; h++) {
                int rl = rl0 + h * 8;
                int b = rb + rl;
                size_t ro = ((size_t)srcd * Bc + b) * 256 + col;
                float2 az = *(const float2*)(g_Az + ro);
                float2 ah = *(const float2*)(g_Ah + ro);
                float2 mp = mprevF ? *(const float2*)(mprevF + (size_t)b * 256 + col)
                                   : make_float2(0.f, 0.f);
                float z0 = sigf(accz[mf][nf][h*2+0] + az.x);
                float z1 = sigf(accz[mf][nf][h*2+1] + az.y);
                float q0 = tanhf(acch[mf][nf][h*2+0] + ah.x);
                float q1 = tanhf(acch[mf][nf][h*2+1] + ah.y);
                float m0 = (1.f - z0) * mp.x + z0 * q0;
                float m1 = (1.f - z1) * mp.y + z1 * q1;
                *(float2*)(moutF + (size_t)b * 256 + col) = make_float2(m0, m1);
                __nv_bfloat16 h0 = __float2bfloat16(m0), h1 = __float2bfloat16(m1);
                size_t po = (planeRowBase + b) * 256 + col;
                *(uint32_t*)(g_mH + po) = packbf2(__bfloat162float(h0), __bfloat162float(h1));
                *(uint32_t*)(g_mL + po) = packbf2(m0 - __bfloat162float(h0), m1 - __bfloat162float(h1));
            }
        }
}

// ------------- scan phase B (HMMA): r GEMM + r*m ---------------------------
#define SB_AH 0
#define SB_AL 10240
#define SB_BH 20480
#define SB_BL 25600
#define SB_DSM 30720
__global__ void k_scanB(int t)
{
    extern __shared__ char smc[];
    uint32_t smb = s2u(smc);
    int tid = threadIdx.x, lane = tid & 31, warp = tid >> 5;
    int wm = warp >> 1, wn = warp & 1;
    int rowBase = blockIdx.x * 128, colBase = blockIdx.y * 64;
    int dir = rowBase >> 11;
    int rb = rowBase & 2047;
    int dstd = dir ? (Tc - 1 - t) : (t + 1);

    const uint4 *aHp[2], *aLp[2];
    uint32_t aStore[2];
#pragma unroll
    for (int j = 0; j < 2; j++) {
        int idx = tid + j * 256;
        int row = idx >> 2, q = idx & 3;
        aStore[j] = (uint32_t)(row * 80 + q * 16);
        size_t pr = (size_t)dir * TB + (size_t)t * Bc + rb + row;
        aHp[j] = (const uint4*)(g_mH + pr * 256 + q * 8);
        aLp[j] = (const uint4*)(g_mL + pr * 256 + q * 8);
    }
    int bRow = tid >> 2, bQ = tid & 3;
    uint32_t bStore = (uint32_t)(bRow * 80 + bQ * 16);
    const uint4* urH = (const uint4*)(g_wH + (size_t)(2944 + colBase + bRow) * 256 + bQ * 8);
    const uint4* urL = (const uint4*)(g_wL + (size_t)(2944 + colBase + bRow) * 256 + bQ * 8);
    uint32_t aOff = aLaneOff(lane, wm), bOff = bLaneOff(lane, wn);

    float acc[2][4][4] = {};
    for (int kc = 0; kc < 8; kc++) {
#pragma unroll
        for (int j = 0; j < 2; j++) {
            *(uint4*)(smc + SB_AH + aStore[j]) = aHp[j][kc * 4];
            *(uint4*)(smc + SB_AL + aStore[j]) = aLp[j][kc * 4];
        }
        *(uint4*)(smc + SB_BH + bStore) = urH[kc * 4];
        *(uint4*)(smc + SB_BL + bStore) = urL[kc * 4];
        __syncthreads();
#pragma unroll
        for (int kk = 0; kk < 2; kk++) {
            uint32_t kb = kk * 32;
            pass_mma(smb + SB_AH + aOff + kb, smb + SB_BH + bOff + kb, acc);
            pass_mma(smb + SB_AH + aOff + kb, smb + SB_BL + bOff + kb, acc);
            pass_mma(smb + SB_AL + aOff + kb, smb + SB_BH + bOff + kb, acc);
        }
        __syncthreads();
    }

    const float* mcurF = (dir ? g_mr : g_mf) + (size_t)t * Bc * 256;
    size_t rmRowBase = (size_t)dir * Bc;
#pragma unroll
    for (int mf = 0; mf < 2; mf++)
#pragma unroll
        for (int nf = 0; nf < 4; nf++) {
            int rl0 = wm * 32 + mf * 16 + (lane >> 2);
            int col = colBase + wn * 32 + nf * 8 + ((lane & 3) << 1);
#pragma unroll
            for (int h = 0; h < 2; h++) {
                int rl = rl0 + h * 8;
                int b = rb + rl;
                float2 ar = *(const float2*)(g_Ar + ((size_t)dstd * Bc + b) * 256 + col);
                float2 mc = *(const float2*)(mcurF + (size_t)b * 256 + col);
                float r0 = sigf(acc[mf][nf][h*2+0] + ar.x);
                float r1 = sigf(acc[mf][nf][h*2+1] + ar.y);
                float rm0 = r0 * mc.x, rm1 = r1 * mc.y;
                __nv_bfloat16 h0 = __float2bfloat16(rm0), h1 = __float2bfloat16(rm1);
                size_t po = (rmRowBase + b) * 256 + col;
                *(uint32_t*)(g_rmH + po) = packbf2(__bfloat162float(h0), __bfloat162float(h1));
                *(uint32_t*)(g_rmL + po) = packbf2(rm0 - __bfloat162float(h0), rm1 - __bfloat162float(h1));
            }
        }
}

// ------------- q-head reduction --------------------------------------------
__global__ void k_qreduce(const int* __restrict__ wid)
{
    int warp = threadIdx.x >> 5, lane = threadIdx.x & 31;
    int row = blockIdx.x * 8 + warp;
    const float* qr = g_logits + (size_t)row * Vc;

    float bv = -3.4e38f; int bi = Vc;
    for (int j = lane; j < Vc; j += 32) {
        float v = qr[j];
        if (v > bv) { bv = v; bi = j; }
    }
#pragma unroll
    for (int o = 16; o; o >>= 1) {
        float ov = __shfl_xor_sync(0xffffffffu, bv, o);
        int   oi = __shfl_xor_sync(0xffffffffu, bi, o);
        if (ov > bv || (ov == bv && oi < bi)) { bv = ov; bi = oi; }
    }
    float se = 0.f;
    for (int j = lane; j < Vc; j += 32) se += expf(qr[j] - bv);
#pragma unroll
    for (int o = 16; o; o >>= 1) se += __shfl_xor_sync(0xffffffffu, se, o);

    __shared__ float sl[8], sc[8];
    if (lane == 0) {
        int d = row >> 11, b = row & (Bc - 1);
        int tgt = wid[b * Dc + d];
        float sel = qr[tgt];
        sl[warp] = (bv + logf(se)) - sel;
        sc[warp] = (bi == tgt) ? 1.f : 0.f;
    }
    __syncthreads();
    if (threadIdx.x == 0) {
        float a = 0.f, c = 0.f;
        for (int w = 0; w < 8; w++) { a += sl[w]; c += sc[w]; }
        g_qpart_loss[blockIdx.x] = a;
        g_qpart_corr[blockIdx.x] = c;
    }
}

// ------------- p-head ------------------------------------------------------
__global__ void k_p(const float* __restrict__ usw, const float* __restrict__ usb)
{
    int warp = threadIdx.x >> 5, lane = threadIdx.x & 31;
    int row = blockIdx.x * 8 + warp;
    int s = row >> 11, b = row & (Bc - 1);

    int xd, c1, c2;
    if (s == 0)       { xd = 0; c1 = -1; c2 = -1; }
    else if (s <= Tc) { xd = s; c1 = s - 1; c2 = -1; }
    else { int j = s - (Tc + 1); xd = Tc - 1 - j; c1 = (j <= Tc - 2) ? (Tc - 2 - j) : -1; c2 = j; }

    const float* px = g_Px + ((size_t)xd * Bc + b) * Hc;
    const float* tp = g_Tp + (size_t)b * Hc;
    const float* f1 = (c1 >= 0) ? (g_Pmf + ((size_t)c1 * Bc + b) * Hc) : (const float*)0;
    const float* f2 = (c2 >= 0) ? (g_Pmr + ((size_t)c2 * Bc + b) * Hc) : (const float*)0;

    float acc = 0.f;
#pragma unroll
    for (int i = 0; i < 2; i++) {
        int n = (lane + 32 * i) * 4;
        float4 v = *(const float4*)(px + n);
        float4 t4 = *(const float4*)(tp + n);
        v.x += t4.x; v.y += t4.y; v.z += t4.z; v.w += t4.w;
        if (f1) { float4 a4 = *(const float4*)(f1 + n); v.x+=a4.x; v.y+=a4.y; v.z+=a4.z; v.w+=a4.w; }
        if (f2) { float4 a4 = *(const float4*)(f2 + n); v.x+=a4.x; v.y+=a4.y; v.z+=a4.z; v.w+=a4.w; }
        v.x = fmaxf(v.x,0.f); v.y = fmaxf(v.y,0.f); v.z = fmaxf(v.z,0.f); v.w = fmaxf(v.w,0.f);
        float4 u = *(const float4*)(usw + n);
        acc += v.x*u.x + v.y*u.y + v.z*u.z + v.w*u.w;
    }
#pragma unroll
    for (int o = 16; o; o >>= 1) acc += __shfl_xor_sync(0xffffffffu, acc, o);

    __shared__ float sl[8], sc[8];
    if (lane == 0) {
        float p = acc + usb[0];
        int tchk = (s < Tc) ? 1 : 0;
        float loss = fmaxf(p, 0.f) - (tchk ? p : 0.f) + log1pf(expf(-fabsf(p)));
        float corr = (((p > 0.f) ? 1 : 0) == tchk) ? 1.f : 0.f;
        sl[warp] = loss; sc[warp] = corr;
    }
    __syncthreads();
    if (threadIdx.x == 0) {
        float a = 0.f, c = 0.f;
        for (int w = 0; w < 8; w++) { a += sl[w]; c += sc[w]; }
        g_ppart_loss[blockIdx.x] = a;
        g_ppart_corr[blockIdx.x] = c;
    }
}

__global__ void k_finalize(float* __restrict__ out)
{
    __shared__ float sq[256], sqc[256], sp[256], spc[256];
    int t = threadIdx.x;
    float a = 0.f, b = 0.f, c = 0.f, d = 0.f;
    for (int i = t; i < QBLOCKS; i += 256) { a += g_qpart_loss[i]; b += g_qpart_corr[i]; }
    for (int i = t; i < PBLOCKS; i += 256) { c += g_ppart_loss[i]; d += g_ppart_corr[i]; }
    sq[t] = a; sqc[t] = b; sp[t] = c; spc[t] = d;
    __syncthreads();
    for (int o = 128; o; o >>= 1) {
        if (t < o) { sq[t]+=sq[t+o]; sqc[t]+=sqc[t+o]; sp[t]+=sp[t+o]; spc[t]+=spc[t+o]; }
        __syncthreads();
    }
    if (t == 0) {
        out[0] = sq[0]  / (float)Bc;
        out[1] = sp[0]  / (float)Bc;
        out[2] = sqc[0] / (float)DB;
        out[3] = spc[0] / (float)SB;
    }
}

// ---------------------------------------------------------------------------
extern "C" void kernel_launch(void* const* d_in, const int* in_sizes, int n_in,
                              void* d_out, int out_size)
{
    const int*   wid      = (const int*)  d_in[0];
    const float* tree_vec = (const float*)d_in[1];
    const float* emb      = (const float*)d_in[2];
    const float* Wz       = (const float*)d_in[3];
    const float* bz       = (const float*)d_in[4];
    const float* Wr       = (const float*)d_in[5];
    const float* Ur       = (const float*)d_in[6];
    const float* br       = (const float*)d_in[7];
    const float* Wh       = (const float*)d_in[8];
    const float* bh       = (const float*)d_in[9];
    const float* W_w      = (const float*)d_in[10];
    const float* W_b      = (const float*)d_in[11];
    const float* U_w      = (const float*)d_in[12];
    const float* U_b      = (const float*)d_in[13];
    const float* Wo_w     = (const float*)d_in[14];
    const float* Wo_b     = (const float*)d_in[15];
    const float* Us_w     = (const float*)d_in[16];
    const float* Us_b     = (const float*)d_in[17];
    float* out = (float*)d_out;

    static int attrDone = 0;
    if (!attrDone) {
        cudaFuncSetAttribute(k_tcg,   cudaFuncAttributeMaxDynamicSharedMemorySize, TCG_DSM);
        cudaFuncSetAttribute(k_scanA, cudaFuncAttributeMaxDynamicSharedMemorySize, SA_DSM);
        cudaFuncSetAttribute(k_scanB, cudaFuncAttributeMaxDynamicSharedMemorySize, SB_DSM);
        attrDone = 1;
    }

    k_split_w<<<WROWS, 256>>>(Wz, Wh, Wr, Ur, U_w, W_w, Wo_w);
    k_split_emb<<<Vc, 256>>>(emb);
    k_tree<<<dim3(Bc, 2), 256>>>(tree_vec, W_w, W_b, U_w, U_b);

    k_tcg<<<dim3(DB/128, 4, 4), 256, TCG_DSM>>>(0, wid, bz, bh, br, Wo_b);

    for (int t = 0; t < Tc; t++) {
        k_scanA<<<dim3(32, 4), 256, SA_DSM>>>(t);
        if (t < Tc - 1)
            k_scanB<<<dim3(32, 4), 256, SB_DSM>>>(t);
    }

    k_tcg<<<dim3(TB/128, 4, 3), 256, TCG_DSM>>>(4, wid, bz, bh, br, Wo_b);
    k_tcg<<<dim3(DB/128, 14, 1), 256, TCG_DSM>>>(7, wid, bz, bh, br, Wo_b);

    k_qreduce<<<QBLOCKS, 256>>>(wid);
    k_p<<<PBLOCKS, 256>>>(Us_w, Us_b);
    k_finalize<<<1, 256>>>(out);
}

// round 5
// speedup vs baseline: 1.8998x; 1.0125x over previous
#include <cuda_runtime.h>
#include <cuda_bf16.h>
#include <math.h>
#include <stdint.h>

#define Bc 2048
#define Dc 24
#define Hc 256
#define Lc 64
#define Vc 780
#define Tc 23
#define Sc 47
#define DB (Dc*Bc)
#define TB (Tc*Bc)
#define SB (Sc*Bc)
#define QP (DB/128)         /* 384 q partials (one per k_qhead CTA) */
#define PBLOCKS (SB/8)
#define WROWS 3200

// ---------------- fp32 scratch ---------------------------------------------
__device__ float g_Az[DB*Hc];
__device__ float g_Ah[DB*Hc];
__device__ float g_Ar[DB*Hc];
__device__ float g_Px[DB*Hc];
__device__ float g_Pq [TB*Hc];
__device__ float g_Pmf[TB*Hc];
__device__ float g_Pmr[TB*Hc];
__device__ float g_Tq[Bc*Hc];
__device__ float g_Tp[Bc*Hc];
__device__ float g_qpart_loss[QP];
__device__ float g_qpart_corr[QP];
__device__ float g_ppart_loss[PBLOCKS];
__device__ float g_ppart_corr[PBLOCKS];
// bf16 split planes
__device__ __nv_bfloat16 g_wH[(size_t)WROWS*Hc];
__device__ __nv_bfloat16 g_wL[(size_t)WROWS*Hc];
__device__ __nv_bfloat16 g_eH[(size_t)Vc*Hc];
__device__ __nv_bfloat16 g_eL[(size_t)Vc*Hc];
__device__ __nv_bfloat16 g_mH[(size_t)2*TB*Hc];   // [dir][t*Bc+b][Hc]
__device__ __nv_bfloat16 g_mL[(size_t)2*TB*Hc];
__device__ __nv_bfloat16 g_rmH[(size_t)2*Bc*Hc];  // [dir][b][Hc]
__device__ __nv_bfloat16 g_rmL[(size_t)2*Bc*Hc];

__device__ __forceinline__ float sigf(float x) { return 1.f / (1.f + expf(-x)); }

// =================== mma.sync core (sm_80+ path) ============================
__device__ __forceinline__ uint32_t s2u(const void* p) {
    uint32_t a;
    asm("{ .reg .u64 t; cvta.to.shared.u64 t, %1; cvt.u32.u64 %0, t; }" : "=r"(a) : "l"(p));
    return a;
}
__device__ __forceinline__ void ldsm4(uint32_t& r0, uint32_t& r1, uint32_t& r2, uint32_t& r3, uint32_t a) {
    asm volatile("ldmatrix.sync.aligned.m8n8.x4.shared.b16 {%0,%1,%2,%3}, [%4];"
        : "=r"(r0), "=r"(r1), "=r"(r2), "=r"(r3) : "r"(a));
}
__device__ __forceinline__ void mma16816(float* d,
    uint32_t a0, uint32_t a1, uint32_t a2, uint32_t a3, uint32_t b0, uint32_t b1) {
    asm volatile("mma.sync.aligned.m16n8k16.row.col.f32.bf16.bf16.f32 "
        "{%0,%1,%2,%3}, {%4,%5,%6,%7}, {%8,%9}, {%0,%1,%2,%3};"
        : "+f"(d[0]), "+f"(d[1]), "+f"(d[2]), "+f"(d[3])
        : "r"(a0), "r"(a1), "r"(a2), "r"(a3), "r"(b0), "r"(b1));
}
__device__ __forceinline__ void pass_mma(uint32_t aAddr, uint32_t bAddr, float acc[2][4][4]) {
    uint32_t b0, b1, b2, b3, b4, b5, b6, b7;
    ldsm4(b0, b1, b2, b3, bAddr);
    ldsm4(b4, b5, b6, b7, bAddr + 1280);
#pragma unroll
    for (int mf = 0; mf < 2; mf++) {
        uint32_t a0, a1, a2, a3;
        ldsm4(a0, a1, a2, a3, aAddr + mf * 1280);
        mma16816(acc[mf][0], a0, a1, a2, a3, b0, b1);
        mma16816(acc[mf][1], a0, a1, a2, a3, b2, b3);
        mma16816(acc[mf][2], a0, a1, a2, a3, b4, b5);
        mma16816(acc[mf][3], a0, a1, a2, a3, b6, b7);
    }
}
__device__ __forceinline__ uint32_t aLaneOff(int lane, int wm) {
    return (uint32_t)((lane & 15) * 80 + (lane >> 4) * 16 + wm * 2560);
}
__device__ __forceinline__ uint32_t bLaneOff(int lane, int wn) {
    return (uint32_t)((((lane & 7) + ((lane >> 4) & 1) * 8)) * 80 + ((lane >> 3) & 1) * 16 + wn * 2560);
}
__device__ __forceinline__ uint32_t packbf2(float a, float b) {
    __nv_bfloat162 v = __floats2bfloat162_rn(a, b);
    return *(uint32_t*)&v;
}
__device__ __forceinline__ float2 unpack2(uint32_t h, uint32_t l) {
    __nv_bfloat162 H = *(__nv_bfloat162*)&h, L = *(__nv_bfloat162*)&l;
    return make_float2(__bfloat162float(H.x) + __bfloat162float(L.x),
                       __bfloat162float(H.y) + __bfloat162float(L.y));
}

// ------------- split/convert kernels ---------------------------------------
__global__ void k_split_w(const float* __restrict__ Wz, const float* __restrict__ Wh,
                          const float* __restrict__ Wr, const float* __restrict__ Ur,
                          const float* __restrict__ U_w, const float* __restrict__ W_w,
                          const float* __restrict__ Wo_w)
{
    int r = blockIdx.x, c = threadIdx.x;
    float v;
    if      (r < 256)  v = Wz[r * 512 + c];
    else if (r < 512)  v = Wh[(r - 256) * 512 + c];
    else if (r < 768)  v = Wr[(r - 512) * 256 + c];
    else if (r < 1024) v = U_w[(r - 768) * 576 + c];
    else if (r < 1280) v = W_w[(r - 1024) * 320 + c];
    else if (r < 1536) v = U_w[(r - 1280) * 576 + 256 + c];
    else if (r < 2432) { int w = r - 1536; v = (w < Vc) ? Wo_w[(size_t)w * 256 + c] : 0.f; }
    else if (r < 2688) v = Wz[(r - 2432) * 512 + 256 + c];
    else if (r < 2944) v = Wh[(r - 2688) * 512 + 256 + c];
    else               v = Ur[(r - 2944) * 256 + c];
    __nv_bfloat16 h = __float2bfloat16(v);
    g_wH[(size_t)r * 256 + c] = h;
    g_wL[(size_t)r * 256 + c] = __float2bfloat16(v - __bfloat162float(h));
}

__global__ void k_split_emb(const float* __restrict__ emb)
{
    int r = blockIdx.x, c = threadIdx.x;
    float v = emb[(size_t)r * 256 + c];
    __nv_bfloat16 h = __float2bfloat16(v);
    g_eH[(size_t)r * 256 + c] = h;
    g_eL[(size_t)r * 256 + c] = __float2bfloat16(v - __bfloat162float(h));
}

// ------------- generic big GEMM (HMMA, CTA 128x64, warp 32x32) -------------
// mode 0-3: A=emb[wid] planes, W seg {0,256,512,768}, out Az/Ah/Ar/Px (+bias)
// mode 4-6: A=m planes, seg {1024,1280,1280}, out Pq/Pmf/Pmr
#define TCG_AH 0
#define TCG_AL 10240
#define TCG_BH 20480
#define TCG_BL 25600
#define TCG_DSM 33792
__global__ void k_tcg(int modeBase, const int* __restrict__ wid,
                      const float* __restrict__ bz, const float* __restrict__ bh,
                      const float* __restrict__ br)
{
    extern __shared__ char smc[];
    uint32_t smb = s2u(smc);
    int tid = threadIdx.x, lane = tid & 31, warp = tid >> 5;
    int wm = warp >> 1, wn = warp & 1;
    int mode = modeBase + blockIdx.z;
    int rowBase = blockIdx.x * 128, colBase = blockIdx.y * 64;

    int wbase; float* outp; const float* bias;
    switch (mode) {
        case 0: wbase = 0;    outp = g_Az;  bias = bz; break;
        case 1: wbase = 256;  outp = g_Ah;  bias = bh; break;
        case 2: wbase = 512;  outp = g_Ar;  bias = br; break;
        case 3: wbase = 768;  outp = g_Px;  bias = 0;  break;
        case 4: wbase = 1024; outp = g_Pq;  bias = 0;  break;
        case 5: wbase = 1280; outp = g_Pmf; bias = 0;  break;
        default: wbase = 1280; outp = g_Pmr; bias = 0; break;
    }

    const uint4 *aHp[2], *aLp[2];
    uint32_t aStore[2];
#pragma unroll
    for (int j = 0; j < 2; j++) {
        int idx = tid + j * 256;
        int row = idx >> 2, q = idx & 3;
        aStore[j] = (uint32_t)(row * 80 + q * 16);
        int rA = rowBase + row;
        if (mode < 4) {
            int d = rA >> 11, b = rA & 2047;
            int sr = wid[b * Dc + d];
            aHp[j] = (const uint4*)(g_eH + (size_t)sr * 256 + q * 8);
            aLp[j] = (const uint4*)(g_eL + (size_t)sr * 256 + q * 8);
        } else {
            size_t rs = (size_t)((mode == 6) ? TB : 0) + rA;
            aHp[j] = (const uint4*)(g_mH + rs * 256 + q * 8);
            aLp[j] = (const uint4*)(g_mL + rs * 256 + q * 8);
        }
    }
    int bRow = tid >> 2, bQ = tid & 3;
    uint32_t bStore = (uint32_t)(bRow * 80 + bQ * 16);
    const uint4* bHp = (const uint4*)(g_wH + (size_t)(wbase + colBase + bRow) * 256 + bQ * 8);
    const uint4* bLp = (const uint4*)(g_wL + (size_t)(wbase + colBase + bRow) * 256 + bQ * 8);

    uint32_t aOff = aLaneOff(lane, wm), bOff = bLaneOff(lane, wn);
    float acc[2][4][4] = {};

    for (int kc = 0; kc < 8; kc++) {
#pragma unroll
        for (int j = 0; j < 2; j++) {
            *(uint4*)(smc + TCG_AH + aStore[j]) = aHp[j][kc * 4];
            *(uint4*)(smc + TCG_AL + aStore[j]) = aLp[j][kc * 4];
        }
        *(uint4*)(smc + TCG_BH + bStore) = bHp[kc * 4];
        *(uint4*)(smc + TCG_BL + bStore) = bLp[kc * 4];
        __syncthreads();
#pragma unroll
        for (int kk = 0; kk < 2; kk++) {
            uint32_t ah = smb + TCG_AH + aOff + kk * 32;
            uint32_t al = smb + TCG_AL + aOff + kk * 32;
            uint32_t bh_ = smb + TCG_BH + bOff + kk * 32;
            uint32_t bl_ = smb + TCG_BL + bOff + kk * 32;
            pass_mma(ah, bh_, acc);
            pass_mma(ah, bl_, acc);
            pass_mma(al, bh_, acc);
        }
        __syncthreads();
    }

    // staged coalesced epilogue
    float* stg = (float*)smc + warp * (32 * 33);
#pragma unroll
    for (int mf = 0; mf < 2; mf++)
#pragma unroll
        for (int nf = 0; nf < 4; nf++) {
            int r = mf * 16 + (lane >> 2);
            int c = nf * 8 + ((lane & 3) << 1);
            stg[r * 33 + c]           = acc[mf][nf][0];
            stg[r * 33 + c + 1]       = acc[mf][nf][1];
            stg[(r + 8) * 33 + c]     = acc[mf][nf][2];
            stg[(r + 8) * 33 + c + 1] = acc[mf][nf][3];
        }
    __syncwarp();
    int colg = colBase + wn * 32 + lane;
    float bval = bias ? bias[colg] : 0.f;
#pragma unroll 8
    for (int r = 0; r < 32; r++) {
        int rowg = rowBase + wm * 32 + r;
        outp[(size_t)rowg * 256 + colg] = stg[r * 33 + lane] + bval;
    }
}

// ------------- tree_vec small GEMMs ----------------------------------------
__global__ void k_tree(const float* __restrict__ tv,
                       const float* __restrict__ W_w, const float* __restrict__ W_b,
                       const float* __restrict__ U_w, const float* __restrict__ U_b)
{
    int b = blockIdx.x, z = blockIdx.y, n = threadIdx.x;
    __shared__ float s_tv[Lc];
    if (n < Lc) s_tv[n] = tv[(size_t)b * Lc + n];
    __syncthreads();
    const float* W; int ld, koff; const float* bias; float* out;
    if (z == 0) { W = W_w; ld = Hc + Lc;   koff = Hc;   bias = W_b; out = g_Tq; }
    else        { W = U_w; ld = 2*Hc + Lc; koff = 2*Hc; bias = U_b; out = g_Tp; }
    const float* wr = W + (size_t)n * ld + koff;
    float s = bias[n];
#pragma unroll
    for (int k = 0; k < Lc; k += 4) {
        float4 w4 = *(const float4*)(wr + k);
        s += s_tv[k]*w4.x + s_tv[k+1]*w4.y + s_tv[k+2]*w4.z + s_tv[k+3]*w4.w;
    }
    out[(size_t)b * Hc + n] = s;
}

// ------------- scan phase A (HMMA): z/mt GEMMs + GRU update ----------------
#define SA_A1H 0
#define SA_A1L 10240
#define SA_A2H 20480
#define SA_A2L 30720
#define SA_BZH 40960
#define SA_BZL 46080
#define SA_BHH 51200
#define SA_BHL 56320
#define SA_DSM 61440
__global__ void k_scanA(int t)
{
    extern __shared__ char smc[];
    uint32_t smb = s2u(smc);
    int tid = threadIdx.x, lane = tid & 31, warp = tid >> 5;
    int wm = warp >> 1, wn = warp & 1;
    int rowBase = blockIdx.x * 128, colBase = blockIdx.y * 64;
    int dir = rowBase >> 11;
    int rb = rowBase & 2047;
    int srcd = dir ? (Tc - t) : t;

    float accz[2][4][4] = {}, acch[2][4][4] = {};

    if (t > 0) {
        const uint4 *m1H[2], *m1L[2], *m2H[2], *m2L[2];
        uint32_t aStore[2];
#pragma unroll
        for (int j = 0; j < 2; j++) {
            int idx = tid + j * 256;
            int row = idx >> 2, q = idx & 3;
            aStore[j] = (uint32_t)(row * 80 + q * 16);
            size_t pr = (size_t)dir * TB + (size_t)(t - 1) * Bc + rb + row;
            m1H[j] = (const uint4*)(g_mH + pr * 256 + q * 8);
            m1L[j] = (const uint4*)(g_mL + pr * 256 + q * 8);
            size_t rr = (size_t)dir * Bc + rb + row;
            m2H[j] = (const uint4*)(g_rmH + rr * 256 + q * 8);
            m2L[j] = (const uint4*)(g_rmL + rr * 256 + q * 8);
        }
        int bRow = tid >> 2, bQ = tid & 3;
        uint32_t bStore = (uint32_t)(bRow * 80 + bQ * 16);
        const uint4* uzH = (const uint4*)(g_wH + (size_t)(2432 + colBase + bRow) * 256 + bQ * 8);
        const uint4* uzL = (const uint4*)(g_wL + (size_t)(2432 + colBase + bRow) * 256 + bQ * 8);
        const uint4* uhH = (const uint4*)(g_wH + (size_t)(2688 + colBase + bRow) * 256 + bQ * 8);
        const uint4* uhL = (const uint4*)(g_wL + (size_t)(2688 + colBase + bRow) * 256 + bQ * 8);
        uint32_t aOff = aLaneOff(lane, wm), bOff = bLaneOff(lane, wn);

        for (int kc = 0; kc < 8; kc++) {
#pragma unroll
            for (int j = 0; j < 2; j++) {
                *(uint4*)(smc + SA_A1H + aStore[j]) = m1H[j][kc * 4];
                *(uint4*)(smc + SA_A1L + aStore[j]) = m1L[j][kc * 4];
                *(uint4*)(smc + SA_A2H + aStore[j]) = m2H[j][kc * 4];
                *(uint4*)(smc + SA_A2L + aStore[j]) = m2L[j][kc * 4];
            }
            *(uint4*)(smc + SA_BZH + bStore) = uzH[kc * 4];
            *(uint4*)(smc + SA_BZL + bStore) = uzL[kc * 4];
            *(uint4*)(smc + SA_BHH + bStore) = uhH[kc * 4];
            *(uint4*)(smc + SA_BHL + bStore) = uhL[kc * 4];
            __syncthreads();
#pragma unroll
            for (int kk = 0; kk < 2; kk++) {
                uint32_t kb = kk * 32;
                pass_mma(smb + SA_A1H + aOff + kb, smb + SA_BZH + bOff + kb, accz);
                pass_mma(smb + SA_A1H + aOff + kb, smb + SA_BZL + bOff + kb, accz);
                pass_mma(smb + SA_A1L + aOff + kb, smb + SA_BZH + bOff + kb, accz);
                pass_mma(smb + SA_A2H + aOff + kb, smb + SA_BHH + bOff + kb, acch);
                pass_mma(smb + SA_A2H + aOff + kb, smb + SA_BHL + bOff + kb, acch);
                pass_mma(smb + SA_A2L + aOff + kb, smb + SA_BHH + bOff + kb, acch);
            }
            __syncthreads();
        }
    }

    // GRU epilogue on accumulator layout; m carried as bf16 hi/lo planes only
    size_t planeRowBase = (size_t)dir * TB + (size_t)t * Bc;
    size_t planePrevBase = (size_t)dir * TB + (size_t)(t - 1) * Bc;
#pragma unroll
    for (int mf = 0; mf < 2; mf++)
#pragma unroll
        for (int nf = 0; nf < 4; nf++) {
            int rl0 = wm * 32 + mf * 16 + (lane >> 2);
            int col = colBase + wn * 32 + nf * 8 + ((lane & 3) << 1);
#pragma unroll
            for (int h = 0; h < 2; h++) {
                int rl = rl0 + h * 8;
                int b = rb + rl;
                size_t ro = ((size_t)srcd * Bc + b) * 256 + col;
                float2 az = *(const float2*)(g_Az + ro);
                float2 ah = *(const float2*)(g_Ah + ro);
                float2 mp = make_float2(0.f, 0.f);
                if (t > 0) {
                    size_t pp = (planePrevBase + b) * 256 + col;
                    mp = unpack2(*(const uint32_t*)(g_mH + pp), *(const uint32_t*)(g_mL + pp));
                }
                float z0 = sigf(accz[mf][nf][h*2+0] + az.x);
                float z1 = sigf(accz[mf][nf][h*2+1] + az.y);
                float q0 = tanhf(acch[mf][nf][h*2+0] + ah.x);
                float q1 = tanhf(acch[mf][nf][h*2+1] + ah.y);
                float m0 = (1.f - z0) * mp.x + z0 * q0;
                float m1 = (1.f - z1) * mp.y + z1 * q1;
                __nv_bfloat16 h0 = __float2bfloat16(m0), h1 = __float2bfloat16(m1);
                size_t po = (planeRowBase + b) * 256 + col;
                *(uint32_t*)(g_mH + po) = packbf2(__bfloat162float(h0), __bfloat162float(h1));
                *(uint32_t*)(g_mL + po) = packbf2(m0 - __bfloat162float(h0), m1 - __bfloat162float(h1));
            }
        }
}

// ------------- scan phase B (HMMA): r GEMM + r*m ---------------------------
#define SB_AH 0
#define SB_AL 10240
#define SB_BH 20480
#define SB_BL 25600
#define SB_DSM 30720
__global__ void k_scanB(int t)
{
    extern __shared__ char smc[];
    uint32_t smb = s2u(smc);
    int tid = threadIdx.x, lane = tid & 31, warp = tid >> 5;
    int wm = warp >> 1, wn = warp & 1;
    int rowBase = blockIdx.x * 128, colBase = blockIdx.y * 64;
    int dir = rowBase >> 11;
    int rb = rowBase & 2047;
    int dstd = dir ? (Tc - 1 - t) : (t + 1);

    const uint4 *aHp[2], *aLp[2];
    uint32_t aStore[2];
#pragma unroll
    for (int j = 0; j < 2; j++) {
        int idx = tid + j * 256;
        int row = idx >> 2, q = idx & 3;
        aStore[j] = (uint32_t)(row * 80 + q * 16);
        size_t pr = (size_t)dir * TB + (size_t)t * Bc + rb + row;
        aHp[j] = (const uint4*)(g_mH + pr * 256 + q * 8);
        aLp[j] = (const uint4*)(g_mL + pr * 256 + q * 8);
    }
    int bRow = tid >> 2, bQ = tid & 3;
    uint32_t bStore = (uint32_t)(bRow * 80 + bQ * 16);
    const uint4* urH = (const uint4*)(g_wH + (size_t)(2944 + colBase + bRow) * 256 + bQ * 8);
    const uint4* urL = (const uint4*)(g_wL + (size_t)(2944 + colBase + bRow) * 256 + bQ * 8);
    uint32_t aOff = aLaneOff(lane, wm), bOff = bLaneOff(lane, wn);

    float acc[2][4][4] = {};
    for (int kc = 0; kc < 8; kc++) {
#pragma unroll
        for (int j = 0; j < 2; j++) {
            *(uint4*)(smc + SB_AH + aStore[j]) = aHp[j][kc * 4];
            *(uint4*)(smc + SB_AL + aStore[j]) = aLp[j][kc * 4];
        }
        *(uint4*)(smc + SB_BH + bStore) = urH[kc * 4];
        *(uint4*)(smc + SB_BL + bStore) = urL[kc * 4];
        __syncthreads();
#pragma unroll
        for (int kk = 0; kk < 2; kk++) {
            uint32_t kb = kk * 32;
            pass_mma(smb + SB_AH + aOff + kb, smb + SB_BH + bOff + kb, acc);
            pass_mma(smb + SB_AH + aOff + kb, smb + SB_BL + bOff + kb, acc);
            pass_mma(smb + SB_AL + aOff + kb, smb + SB_BH + bOff + kb, acc);
        }
        __syncthreads();
    }

    size_t mcurBase = (size_t)dir * TB + (size_t)t * Bc;
    size_t rmRowBase = (size_t)dir * Bc;
#pragma unroll
    for (int mf = 0; mf < 2; mf++)
#pragma unroll
        for (int nf = 0; nf < 4; nf++) {
            int rl0 = wm * 32 + mf * 16 + (lane >> 2);
            int col = colBase + wn * 32 + nf * 8 + ((lane & 3) << 1);
#pragma unroll
            for (int h = 0; h < 2; h++) {
                int rl = rl0 + h * 8;
                int b = rb + rl;
                float2 ar = *(const float2*)(g_Ar + ((size_t)dstd * Bc + b) * 256 + col);
                size_t pc = (mcurBase + b) * 256 + col;
                float2 mc = unpack2(*(const uint32_t*)(g_mH + pc), *(const uint32_t*)(g_mL + pc));
                float r0 = sigf(acc[mf][nf][h*2+0] + ar.x);
                float r1 = sigf(acc[mf][nf][h*2+1] + ar.y);
                float rm0 = r0 * mc.x, rm1 = r1 * mc.y;
                __nv_bfloat16 h0 = __float2bfloat16(rm0), h1 = __float2bfloat16(rm1);
                size_t po = (rmRowBase + b) * 256 + col;
                *(uint32_t*)(g_rmH + po) = packbf2(__bfloat162float(h0), __bfloat162float(h1));
                *(uint32_t*)(g_rmL + po) = packbf2(rm0 - __bfloat162float(h0), rm1 - __bfloat162float(h1));
            }
        }
}

// ------------- fused q-head: logits GEMM + online logsumexp/argmax ---------
// One CTA = 128 rows x all 832 weight cols (780 valid). A resident in smem.
#define QH_AH   0                /* 8 chunks x 10240 = 81920 */
#define QH_AL   81920
#define QH_BH   163840           /* 5120 */
#define QH_BL   168960           /* 5120 */
#define QH_STG  174080           /* 128*65*4 = 33280 */
#define QH_BIAS 207360           /* 64*4 */
#define QH_RED  207616           /* 2*128*4 = 1024 */
#define QH_DSM  208640
__global__ void k_qhead(const int* __restrict__ wid, const float* __restrict__ Wob)
{
    extern __shared__ char smc[];
    uint32_t smb = s2u(smc);
    int tid = threadIdx.x, lane = tid & 31, warp = tid >> 5;
    int wm = warp >> 1, wn = warp & 1;
    int rowBase = blockIdx.x * 128;

    // stage A = split(relu(Pq[d-1]+Tq)) resident for all 8 K-chunks
    for (int it = 0; it < 16; it++) {
        int idx = tid + it * 256;          // 0..4095
        int row = idx >> 5, rem = idx & 31, kc = rem >> 2, q = rem & 3;
        int rA = rowBase + row, d = rA >> 11, b = rA & 2047;
        int k0 = kc * 32 + q * 8;
        const float4* tq = (const float4*)(g_Tq + (size_t)b * 256 + k0);
        float4 v0 = tq[0], v1 = tq[1];
        if (d) {
            const float4* pq = (const float4*)(g_Pq + ((size_t)(d - 1) * Bc + b) * 256 + k0);
            float4 p0 = pq[0], p1 = pq[1];
            v0.x += p0.x; v0.y += p0.y; v0.z += p0.z; v0.w += p0.w;
            v1.x += p1.x; v1.y += p1.y; v1.z += p1.z; v1.w += p1.w;
        }
        float vv[8] = { fmaxf(v0.x,0.f), fmaxf(v0.y,0.f), fmaxf(v0.z,0.f), fmaxf(v0.w,0.f),
                        fmaxf(v1.x,0.f), fmaxf(v1.y,0.f), fmaxf(v1.z,0.f), fmaxf(v1.w,0.f) };
        union { uint4 u; __nv_bfloat16 b8[8]; } Hx, Lx;
#pragma unroll
        for (int e = 0; e < 8; e++) {
            Hx.b8[e] = __float2bfloat16(vv[e]);
            Lx.b8[e] = __float2bfloat16(vv[e] - __bfloat162float(Hx.b8[e]));
        }
        uint32_t off = (uint32_t)(kc * 10240 + row * 80 + q * 16);
        *(uint4*)(smc + QH_AH + off) = Hx.u;
        *(uint4*)(smc + QH_AL + off) = Lx.u;
    }
    __syncthreads();

    // per-thread online-LSE state: thread pair (2r, 2r+1) owns row r halves
    int myrow = tid >> 1, half = tid & 1;
    int rA0 = rowBase + myrow;
    int tgt = wid[(rA0 & 2047) * Dc + (rA0 >> 11)];
    float runMax = -3.4e38f, runSum = 0.f, sel = 0.f;
    int runIdx = Vc;

    uint32_t aOff = aLaneOff(lane, wm), bOff = bLaneOff(lane, wn);
    int bRow = tid >> 2, bQ = tid & 3;
    uint32_t bStore = (uint32_t)(bRow * 80 + bQ * 16);
    float* stg = (float*)(smc + QH_STG);
    float* s_bias = (float*)(smc + QH_BIAS);

    for (int cb = 0; cb < 13; cb++) {
        if (tid < 64) {
            int colg = cb * 64 + tid;
            s_bias[tid] = (colg < Vc) ? Wob[colg] : 0.f;
        }
        float acc[2][4][4] = {};
        const uint4* bh = (const uint4*)(g_wH + (size_t)(1536 + cb * 64 + bRow) * 256 + bQ * 8);
        const uint4* bl = (const uint4*)(g_wL + (size_t)(1536 + cb * 64 + bRow) * 256 + bQ * 8);
        for (int kc = 0; kc < 8; kc++) {
            *(uint4*)(smc + QH_BH + bStore) = bh[kc * 4];
            *(uint4*)(smc + QH_BL + bStore) = bl[kc * 4];
            __syncthreads();
            uint32_t aBaseH = smb + QH_AH + kc * 10240 + aOff;
            uint32_t aBaseL = smb + QH_AL + kc * 10240 + aOff;
#pragma unroll
            for (int kk = 0; kk < 2; kk++) {
                uint32_t kb = kk * 32;
                pass_mma(aBaseH + kb, smb + QH_BH + bOff + kb, acc);
                pass_mma(aBaseH + kb, smb + QH_BL + bOff + kb, acc);
                pass_mma(aBaseL + kb, smb + QH_BH + bOff + kb, acc);
            }
            __syncthreads();
        }
        // stage tile 128x64 (stride 65)
#pragma unroll
        for (int mf = 0; mf < 2; mf++)
#pragma unroll
            for (int nf = 0; nf < 4; nf++) {
                int r = wm * 32 + mf * 16 + (lane >> 2);
                int c = wn * 32 + nf * 8 + ((lane & 3) << 1);
                stg[r * 65 + c]           = acc[mf][nf][0];
                stg[r * 65 + c + 1]       = acc[mf][nf][1];
                stg[(r + 8) * 65 + c]     = acc[mf][nf][2];
                stg[(r + 8) * 65 + c + 1] = acc[mf][nf][3];
            }
        __syncthreads();
        // online LSE/argmax update over this thread's 32 cols
        int colBaseT = cb * 64 + half * 32;
#pragma unroll 8
        for (int j = 0; j < 32; j++) {
            int col = colBaseT + j;
            if (col < Vc) {
                float v = stg[myrow * 65 + half * 32 + j] + s_bias[half * 32 + j];
                if (v > runMax) {
                    runSum = runSum * expf(runMax - v) + 1.f;
                    runMax = v; runIdx = col;
                } else {
                    runSum += expf(v - runMax);
                }
                if (col == tgt) sel = v;
            }
        }
        __syncthreads();
    }

    // merge halves (partner lane = tid^1, same warp)
    float oMax = __shfl_xor_sync(0xffffffffu, runMax, 1);
    float oSum = __shfl_xor_sync(0xffffffffu, runSum, 1);
    float oSel = __shfl_xor_sync(0xffffffffu, sel, 1);
    int   oIdx = __shfl_xor_sync(0xffffffffu, runIdx, 1);
    float M = fmaxf(runMax, oMax);
    float S = runSum * expf(runMax - M) + oSum * expf(oMax - M);
    int I = (oMax > runMax || (oMax == runMax && oIdx < runIdx)) ? oIdx : runIdx;
    float SEL = sel + oSel;

    float* lred = (float*)(smc + QH_RED);
    float* cred = lred + 128;
    if (half == 0) {
        lred[myrow] = (M + logf(S)) - SEL;
        cred[myrow] = (I == tgt) ? 1.f : 0.f;
    }
    __syncthreads();
    for (int o = 64; o; o >>= 1) {
        if (tid < o) { lred[tid] += lred[tid + o]; cred[tid] += cred[tid + o]; }
        __syncthreads();
    }
    if (tid == 0) {
        g_qpart_loss[blockIdx.x] = lred[0];
        g_qpart_corr[blockIdx.x] = cred[0];
    }
}

// ------------- p-head ------------------------------------------------------
__global__ void k_p(const float* __restrict__ usw, const float* __restrict__ usb)
{
    int warp = threadIdx.x >> 5, lane = threadIdx.x & 31;
    int row = blockIdx.x * 8 + warp;
    int s = row >> 11, b = row & (Bc - 1);

    int xd, c1, c2;
    if (s == 0)       { xd = 0; c1 = -1; c2 = -1; }
    else if (s <= Tc) { xd = s; c1 = s - 1; c2 = -1; }
    else { int j = s - (Tc + 1); xd = Tc - 1 - j; c1 = (j <= Tc - 2) ? (Tc - 2 - j) : -1; c2 = j; }

    const float* px = g_Px + ((size_t)xd * Bc + b) * Hc;
    const float* tp = g_Tp + (size_t)b * Hc;
    const float* f1 = (c1 >= 0) ? (g_Pmf + ((size_t)c1 * Bc + b) * Hc) : (const float*)0;
    const float* f2 = (c2 >= 0) ? (g_Pmr + ((size_t)c2 * Bc + b) * Hc) : (const float*)0;

    float acc = 0.f;
#pragma unroll
    for (int i = 0; i < 2; i++) {
        int n = (lane + 32 * i) * 4;
        float4 v = *(const float4*)(px + n);
        float4 t4 = *(const float4*)(tp + n);
        v.x += t4.x; v.y += t4.y; v.z += t4.z; v.w += t4.w;
        if (f1) { float4 a4 = *(const float4*)(f1 + n); v.x+=a4.x; v.y+=a4.y; v.z+=a4.z; v.w+=a4.w; }
        if (f2) { float4 a4 = *(const float4*)(f2 + n); v.x+=a4.x; v.y+=a4.y; v.z+=a4.z; v.w+=a4.w; }
        v.x = fmaxf(v.x,0.f); v.y = fmaxf(v.y,0.f); v.z = fmaxf(v.z,0.f); v.w = fmaxf(v.w,0.f);
        float4 u = *(const float4*)(usw + n);
        acc += v.x*u.x + v.y*u.y + v.z*u.z + v.w*u.w;
    }
#pragma unroll
    for (int o = 16; o; o >>= 1) acc += __shfl_xor_sync(0xffffffffu, acc, o);

    __shared__ float sl[8], sc[8];
    if (lane == 0) {
        float p = acc + usb[0];
        int tchk = (s < Tc) ? 1 : 0;
        float loss = fmaxf(p, 0.f) - (tchk ? p : 0.f) + log1pf(expf(-fabsf(p)));
        float corr = (((p > 0.f) ? 1 : 0) == tchk) ? 1.f : 0.f;
        sl[warp] = loss; sc[warp] = corr;
    }
    __syncthreads();
    if (threadIdx.x == 0) {
        float a = 0.f, c = 0.f;
        for (int w = 0; w < 8; w++) { a += sl[w]; c += sc[w]; }
        g_ppart_loss[blockIdx.x] = a;
        g_ppart_corr[blockIdx.x] = c;
    }
}

__global__ void k_finalize(float* __restrict__ out)
{
    __shared__ float sq[256], sqc[256], sp[256], spc[256];
    int t = threadIdx.x;
    float a = 0.f, b = 0.f, c = 0.f, d = 0.f;
    for (int i = t; i < QP; i += 256) { a += g_qpart_loss[i]; b += g_qpart_corr[i]; }
    for (int i = t; i < PBLOCKS; i += 256) { c += g_ppart_loss[i]; d += g_ppart_corr[i]; }
    sq[t] = a; sqc[t] = b; sp[t] = c; spc[t] = d;
    __syncthreads();
    for (int o = 128; o; o >>= 1) {
        if (t < o) { sq[t]+=sq[t+o]; sqc[t]+=sqc[t+o]; sp[t]+=sp[t+o]; spc[t]+=spc[t+o]; }
        __syncthreads();
    }
    if (t == 0) {
        out[0] = sq[0]  / (float)Bc;
        out[1] = sp[0]  / (float)Bc;
        out[2] = sqc[0] / (float)DB;
        out[3] = spc[0] / (float)SB;
    }
}

// ---------------------------------------------------------------------------
extern "C" void kernel_launch(void* const* d_in, const int* in_sizes, int n_in,
                              void* d_out, int out_size)
{
    const int*   wid      = (const int*)  d_in[0];
    const float* tree_vec = (const float*)d_in[1];
    const float* emb      = (const float*)d_in[2];
    const float* Wz       = (const float*)d_in[3];
    const float* bz       = (const float*)d_in[4];
    const float* Wr       = (const float*)d_in[5];
    const float* Ur       = (const float*)d_in[6];
    const float* br       = (const float*)d_in[7];
    const float* Wh       = (const float*)d_in[8];
    const float* bh       = (const float*)d_in[9];
    const float* W_w      = (const float*)d_in[10];
    const float* W_b      = (const float*)d_in[11];
    const float* U_w      = (const float*)d_in[12];
    const float* U_b      = (const float*)d_in[13];
    const float* Wo_w     = (const float*)d_in[14];
    const float* Wo_b     = (const float*)d_in[15];
    const float* Us_w     = (const float*)d_in[16];
    const float* Us_b     = (const float*)d_in[17];
    float* out = (float*)d_out;

    cudaFuncSetAttribute(k_tcg,   cudaFuncAttributeMaxDynamicSharedMemorySize, TCG_DSM);
    cudaFuncSetAttribute(k_scanA, cudaFuncAttributeMaxDynamicSharedMemorySize, SA_DSM);
    cudaFuncSetAttribute(k_scanB, cudaFuncAttributeMaxDynamicSharedMemorySize, SB_DSM);
    cudaFuncSetAttribute(k_qhead, cudaFuncAttributeMaxDynamicSharedMemorySize, QH_DSM);

    k_split_w<<<WROWS, 256>>>(Wz, Wh, Wr, Ur, U_w, W_w, Wo_w);
    k_split_emb<<<Vc, 256>>>(emb);
    k_tree<<<dim3(Bc, 2), 256>>>(tree_vec, W_w, W_b, U_w, U_b);

    k_tcg<<<dim3(DB/128, 4, 4), 256, TCG_DSM>>>(0, wid, bz, bh, br);

    for (int t = 0; t < Tc; t++) {
        k_scanA<<<dim3(32, 4), 256, SA_DSM>>>(t);
        if (t < Tc - 1)
            k_scanB<<<dim3(32, 4), 256, SB_DSM>>>(t);
    }

    k_tcg<<<dim3(TB/128, 4, 3), 256, TCG_DSM>>>(4, wid, bz, bh, br);
    k_qhead<<<DB/128, 256, QH_DSM>>>(wid, Wo_b);

    k_p<<<PBLOCKS, 256>>>(Us_w, Us_b);
    k_finalize<<<1, 256>>>(out);
}